// round 5
// baseline (speedup 1.0000x reference)
#include <cuda_runtime.h>

#define N_NODES 100000
#define D       64
#define N_EDGES 1250000

// ---- scratch (allocation-free rule: __device__ globals) ----
__device__ __align__(16) float g_agg[N_NODES * D];   // scatter-sum of X[src] at dst
__device__ __align__(16) float g_h[N_NODES * D];     // relu(agg@Wl + b + X@Wr)
__device__ __align__(16) float g_gg[N_NODES * D];    // scatter-sum of diff^2 at src
__device__ float g_indeg[N_NODES];
__device__ float g_outdeg[N_NODES];
__device__ int   g_idx64;                            // 1 if edge_index is int64

// Edge accessor robust to int32-vs-int64 edge_index (JAX x64-off ships int32
// even when the reference asks for int64 — reading it as int64 was the R2-R4
// OOB trap).
__device__ __forceinline__ void load_edge(const void* __restrict__ ei,
                                          long long e, int is64,
                                          int& r, int& c) {
    if (is64) {
        const long long* p = (const long long*)ei;
        r = (int)p[e];
        c = (int)p[N_EDGES + e];
    } else {
        const int* p = (const int*)ei;
        r = p[e];
        c = p[N_EDGES + e];
    }
}

// ---------------------------------------------------------------------------
// K-1: dtype detect (1 thread). First 32 int64-interpreted values all in
// [0, N_NODES) => genuinely int64; otherwise int32 pairs.
// Reads only 256 bytes — in-bounds for either dtype.
// ---------------------------------------------------------------------------
__global__ void k_detect(const long long* __restrict__ ei64) {
    int ok = 1;
    for (int i = 0; i < 32; i++) {
        long long v = ei64[i];
        if (v < 0 || v >= N_NODES) { ok = 0; break; }
    }
    g_idx64 = ok;
}

// ---------------------------------------------------------------------------
// K0: zero the accumulators (must run every graph replay)
// ---------------------------------------------------------------------------
__global__ void k_zero() {
    int i = blockIdx.x * blockDim.x + threadIdx.x;
    int stride = gridDim.x * blockDim.x;
    float4 z = make_float4(0.f, 0.f, 0.f, 0.f);
    float4* a4 = reinterpret_cast<float4*>(g_agg);
    float4* g4 = reinterpret_cast<float4*>(g_gg);
    const int n4 = N_NODES * D / 4;
    for (int idx = i; idx < n4; idx += stride) { a4[idx] = z; g4[idx] = z; }
    for (int idx = i; idx < N_NODES; idx += stride) { g_indeg[idx] = 0.f; g_outdeg[idx] = 0.f; }
}

// ---------------------------------------------------------------------------
// K1: degree counts (in-degree at col/dst, out-degree at row/src)
// ---------------------------------------------------------------------------
__global__ void k_deg(const void* __restrict__ ei) {
    int e = blockIdx.x * blockDim.x + threadIdx.x;
    if (e >= N_EDGES) return;
    int is64 = g_idx64;
    int r, c;
    load_edge(ei, e, is64, r, c);
    atomicAdd(&g_outdeg[r], 1.f);
    atomicAdd(&g_indeg[c], 1.f);
}

// ---------------------------------------------------------------------------
// K2: scatter-sum X[row] into g_agg[col]. 16 lanes (float4 load + 4 scalar
//     atomicAdds) per edge.
// ---------------------------------------------------------------------------
__global__ void k_scatter(const float4* __restrict__ X4,
                          const void* __restrict__ ei) {
    long long gtid = (long long)blockIdx.x * blockDim.x + threadIdx.x;
    long long e = gtid >> 4;      // edge id
    int l = (int)(gtid & 15);     // float4 slot within the 64-float row
    if (e >= N_EDGES) return;
    int is64 = g_idx64;
    int r, c;
    load_edge(ei, e, is64, r, c);
    float4 v = X4[(long long)r * 16 + l];
    float* dst = &g_agg[(long long)c * 64 + l * 4];
    atomicAdd(dst + 0, v.x);
    atomicAdd(dst + 1, v.y);
    atomicAdd(dst + 2, v.z);
    atomicAdd(dst + 3, v.w);
}

// ---------------------------------------------------------------------------
// K3: h = relu( (agg/indeg) @ Wl + b + X @ Wr ), Wl/Wr resident in SMEM.
//     256 threads = 4 nodes x 64 output dims per iteration.
// ---------------------------------------------------------------------------
__global__ __launch_bounds__(256) void k_h(const float* __restrict__ X,
                                           const float* __restrict__ Wl,
                                           const float* __restrict__ Wr,
                                           const float* __restrict__ b) {
    __shared__ float sWl[D * D];
    __shared__ float sWr[D * D];
    __shared__ float sb[D];
    __shared__ float sa[4][D];
    __shared__ float sx[4][D];

    int t = threadIdx.x;
    for (int i = t; i < D * D; i += 256) { sWl[i] = Wl[i]; sWr[i] = Wr[i]; }
    if (t < D) sb[t] = b[t];
    __syncthreads();

    int ln = t >> 6;      // 0..3 (node within tile)
    int j  = t & 63;      // output dim

    for (int base = blockIdx.x * 4; base < N_NODES; base += gridDim.x * 4) {
        int node = base + ln;
        float invd = 1.f / fmaxf(g_indeg[node], 1.f);
        sa[ln][j] = g_agg[(long long)node * 64 + j] * invd;
        sx[ln][j] = X[(long long)node * 64 + j];
        __syncthreads();

        float acc = sb[j];
#pragma unroll
        for (int k = 0; k < D; k++) {
            acc += sa[ln][k] * sWl[k * 64 + j] + sx[ln][k] * sWr[k * 64 + j];
        }
        g_h[(long long)node * 64 + j] = fmaxf(acc, 0.f);
        __syncthreads();
    }
}

// ---------------------------------------------------------------------------
// K4: per-edge (h[row]-h[col])^2, scatter-sum at row. 16 lanes per edge.
// ---------------------------------------------------------------------------
__global__ void k_edge(const void* __restrict__ ei) {
    long long gtid = (long long)blockIdx.x * blockDim.x + threadIdx.x;
    long long e = gtid >> 4;
    int l = (int)(gtid & 15);
    if (e >= N_EDGES) return;
    int is64 = g_idx64;
    int r, c;
    load_edge(ei, e, is64, r, c);
    const float4* h4 = reinterpret_cast<const float4*>(g_h);
    float4 u = h4[(long long)r * 16 + l];
    float4 v = h4[(long long)c * 16 + l];
    float dx = u.x - v.x, dy = u.y - v.y, dz = u.z - v.z, dw = u.w - v.w;
    float* dst = &g_gg[(long long)r * 64 + l * 4];
    atomicAdd(dst + 0, dx * dx);
    atomicAdd(dst + 1, dy * dy);
    atomicAdd(dst + 2, dz * dz);
    atomicAdd(dst + 3, dw * dw);
}

// ---------------------------------------------------------------------------
// K5: gg = tanh(gg_sum / max(outdeg,1))
// ---------------------------------------------------------------------------
__global__ void k_final(float* __restrict__ out) {
    int i = blockIdx.x * blockDim.x + threadIdx.x;
    int stride = gridDim.x * blockDim.x;
    for (int idx = i; idx < N_NODES * D; idx += stride) {
        int node = idx >> 6;
        float m = g_gg[idx] / fmaxf(g_outdeg[node], 1.f);
        out[idx] = tanhf(m);
    }
}

// ---------------------------------------------------------------------------
extern "C" void kernel_launch(void* const* d_in, const int* in_sizes, int n_in,
                              void* d_out, int out_size) {
    const float* X  = (const float*)d_in[0];
    const void*  ei = d_in[1];
    const float* Wl = (const float*)d_in[2];
    const float* Wr = (const float*)d_in[3];
    const float* b  = (const float*)d_in[4];
    float* out = (float*)d_out;

    k_detect<<<1, 1>>>((const long long*)ei);
    k_zero<<<2048, 256>>>();
    k_deg<<<(N_EDGES + 255) / 256, 256>>>(ei);
    {
        long long total = (long long)N_EDGES * 16;
        int blocks = (int)((total + 255) / 256);
        k_scatter<<<blocks, 256>>>((const float4*)X, ei);
    }
    k_h<<<888, 256>>>(X, Wl, Wr, b);
    {
        long long total = (long long)N_EDGES * 16;
        int blocks = (int)((total + 255) / 256);
        k_edge<<<blocks, 256>>>(ei);
    }
    k_final<<<2048, 256>>>(out);
}

// round 6
// speedup vs baseline: 2.0533x; 2.0533x over previous
#include <cuda_runtime.h>

#define N_NODES 100000
#define D       64
#define N_EDGES 1250000

// ---- scratch (allocation-free rule: __device__ globals) ----
__device__ __align__(16) float g_agg[N_NODES * D];   // scatter-sum of X[src] at dst
__device__ __align__(16) float g_h[N_NODES * D];     // relu(agg@Wl + b + X@Wr)
__device__ __align__(16) float g_gg[N_NODES * D];    // scatter-sum of diff^2 at src
__device__ float g_indeg[N_NODES];
__device__ float g_outdeg[N_NODES];
__device__ int   g_idx64;                            // 1 if edge_index is int64

// Vectorized global reduction: one RED.128 instead of 4 scalar REDGs.
// (R2's trap was the int64 OOB read, not this instruction — R3 proved scalar
// atomics trapped identically under the same OOB.)
__device__ __forceinline__ void red_add_v4(float* dst, float a, float b,
                                           float c, float d) {
    asm volatile(
        "{\n\t"
        ".reg .u64 p;\n\t"
        "cvta.to.global.u64 p, %0;\n\t"
        "red.global.add.v4.f32 [p], {%1, %2, %3, %4};\n\t"
        "}"
        :: "l"(dst), "f"(a), "f"(b), "f"(c), "f"(d)
        : "memory");
}

// Edge accessor robust to int32-vs-int64 edge_index (JAX x64-off ships int32
// even when the reference asks for int64).
__device__ __forceinline__ void load_edge(const void* __restrict__ ei,
                                          long long e, int is64,
                                          int& r, int& c) {
    if (is64) {
        const long long* p = (const long long*)ei;
        r = (int)p[e];
        c = (int)p[N_EDGES + e];
    } else {
        const int* p = (const int*)ei;
        r = p[e];
        c = p[N_EDGES + e];
    }
}

// ---------------------------------------------------------------------------
// K-1: dtype detect (1 thread). First 32 int64-interpreted values all in
// [0, N_NODES) => genuinely int64; otherwise int32 pairs.
// ---------------------------------------------------------------------------
__global__ void k_detect(const long long* __restrict__ ei64) {
    int ok = 1;
    for (int i = 0; i < 32; i++) {
        long long v = ei64[i];
        if (v < 0 || v >= N_NODES) { ok = 0; break; }
    }
    g_idx64 = ok;
}

// ---------------------------------------------------------------------------
// K0: zero the accumulators (must run every graph replay)
// ---------------------------------------------------------------------------
__global__ void k_zero() {
    int i = blockIdx.x * blockDim.x + threadIdx.x;
    int stride = gridDim.x * blockDim.x;
    float4 z = make_float4(0.f, 0.f, 0.f, 0.f);
    float4* a4 = reinterpret_cast<float4*>(g_agg);
    float4* g4 = reinterpret_cast<float4*>(g_gg);
    const int n4 = N_NODES * D / 4;
    for (int idx = i; idx < n4; idx += stride) { a4[idx] = z; g4[idx] = z; }
    for (int idx = i; idx < N_NODES; idx += stride) { g_indeg[idx] = 0.f; g_outdeg[idx] = 0.f; }
}

// ---------------------------------------------------------------------------
// K2: scatter-sum X[row] into g_agg[col] + fused in-degree count.
//     16 lanes per edge: one LDG.128 + one RED.128 each.
// ---------------------------------------------------------------------------
__global__ void k_scatter(const float4* __restrict__ X4,
                          const void* __restrict__ ei) {
    long long gtid = (long long)blockIdx.x * blockDim.x + threadIdx.x;
    long long e = gtid >> 4;      // edge id
    int l = (int)(gtid & 15);     // float4 slot within the 64-float row
    if (e >= N_EDGES) return;
    int is64 = g_idx64;
    int r, c;
    load_edge(ei, e, is64, r, c);
    float4 v = X4[(long long)r * 16 + l];
    red_add_v4(&g_agg[(long long)c * 64 + l * 4], v.x, v.y, v.z, v.w);
    if (l == 0) atomicAdd(&g_indeg[c], 1.f);
}

// ---------------------------------------------------------------------------
// K3: h = relu( (agg/indeg) @ Wl + b + X @ Wr ), Wl/Wr resident in SMEM.
// ---------------------------------------------------------------------------
__global__ __launch_bounds__(256) void k_h(const float* __restrict__ X,
                                           const float* __restrict__ Wl,
                                           const float* __restrict__ Wr,
                                           const float* __restrict__ b) {
    __shared__ float sWl[D * D];
    __shared__ float sWr[D * D];
    __shared__ float sb[D];
    __shared__ float sa[4][D];
    __shared__ float sx[4][D];

    int t = threadIdx.x;
    for (int i = t; i < D * D; i += 256) { sWl[i] = Wl[i]; sWr[i] = Wr[i]; }
    if (t < D) sb[t] = b[t];
    __syncthreads();

    int ln = t >> 6;      // 0..3 (node within tile)
    int j  = t & 63;      // output dim

    for (int base = blockIdx.x * 4; base < N_NODES; base += gridDim.x * 4) {
        int node = base + ln;
        float invd = 1.f / fmaxf(g_indeg[node], 1.f);
        sa[ln][j] = g_agg[(long long)node * 64 + j] * invd;
        sx[ln][j] = X[(long long)node * 64 + j];
        __syncthreads();

        float acc = sb[j];
#pragma unroll
        for (int k = 0; k < D; k++) {
            acc += sa[ln][k] * sWl[k * 64 + j] + sx[ln][k] * sWr[k * 64 + j];
        }
        g_h[(long long)node * 64 + j] = fmaxf(acc, 0.f);
        __syncthreads();
    }
}

// ---------------------------------------------------------------------------
// K4: per-edge (h[row]-h[col])^2, scatter-sum at row + fused out-degree.
// ---------------------------------------------------------------------------
__global__ void k_edge(const void* __restrict__ ei) {
    long long gtid = (long long)blockIdx.x * blockDim.x + threadIdx.x;
    long long e = gtid >> 4;
    int l = (int)(gtid & 15);
    if (e >= N_EDGES) return;
    int is64 = g_idx64;
    int r, c;
    load_edge(ei, e, is64, r, c);
    const float4* h4 = reinterpret_cast<const float4*>(g_h);
    float4 u = h4[(long long)r * 16 + l];
    float4 v = h4[(long long)c * 16 + l];
    float dx = u.x - v.x, dy = u.y - v.y, dz = u.z - v.z, dw = u.w - v.w;
    red_add_v4(&g_gg[(long long)r * 64 + l * 4],
               dx * dx, dy * dy, dz * dz, dw * dw);
    if (l == 0) atomicAdd(&g_outdeg[r], 1.f);
}

// ---------------------------------------------------------------------------
// K5: gg = tanh(gg_sum / max(outdeg,1))
// ---------------------------------------------------------------------------
__global__ void k_final(float* __restrict__ out) {
    int i = blockIdx.x * blockDim.x + threadIdx.x;
    int stride = gridDim.x * blockDim.x;
    for (int idx = i; idx < N_NODES * D; idx += stride) {
        int node = idx >> 6;
        float m = g_gg[idx] / fmaxf(g_outdeg[node], 1.f);
        out[idx] = tanhf(m);
    }
}

// ---------------------------------------------------------------------------
extern "C" void kernel_launch(void* const* d_in, const int* in_sizes, int n_in,
                              void* d_out, int out_size) {
    const float* X  = (const float*)d_in[0];
    const void*  ei = d_in[1];
    const float* Wl = (const float*)d_in[2];
    const float* Wr = (const float*)d_in[3];
    const float* b  = (const float*)d_in[4];
    float* out = (float*)d_out;

    k_detect<<<1, 1>>>((const long long*)ei);
    k_zero<<<2048, 256>>>();
    {
        long long total = (long long)N_EDGES * 16;
        int blocks = (int)((total + 255) / 256);
        k_scatter<<<blocks, 256>>>((const float4*)X, ei);
    }
    k_h<<<888, 256>>>(X, Wl, Wr, b);
    {
        long long total = (long long)N_EDGES * 16;
        int blocks = (int)((total + 255) / 256);
        k_edge<<<blocks, 256>>>(ei);
    }
    k_final<<<2048, 256>>>(out);
}

// round 7
// speedup vs baseline: 2.7764x; 1.3522x over previous
#include <cuda_runtime.h>

#define N_NODES 100000
#define D       64
#define N_EDGES 1250000

// ---- scratch (allocation-free rule: __device__ globals) ----
__device__ __align__(16) float g_agg[N_NODES * D];   // scatter-sum of X[src] at dst
__device__ __align__(16) float g_h[N_NODES * D];     // relu(agg@Wl + b + X@Wr)
__device__ __align__(16) float g_gg[N_NODES * D];    // scatter-sum of diff^2 at src
__device__ float g_indeg[N_NODES];
__device__ float g_outdeg[N_NODES];
__device__ int   g_idx64;                            // 1 if edge_index is int64

// Vectorized global reduction: one RED.128 instead of 4 scalar REDGs.
__device__ __forceinline__ void red_add_v4(float* dst, float a, float b,
                                           float c, float d) {
    asm volatile(
        "{\n\t"
        ".reg .u64 p;\n\t"
        "cvta.to.global.u64 p, %0;\n\t"
        "red.global.add.v4.f32 [p], {%1, %2, %3, %4};\n\t"
        "}"
        :: "l"(dst), "f"(a), "f"(b), "f"(c), "f"(d)
        : "memory");
}

// Edge accessor robust to int32-vs-int64 edge_index.
__device__ __forceinline__ void load_edge(const void* __restrict__ ei,
                                          long long e, int is64,
                                          int& r, int& c) {
    if (is64) {
        const long long* p = (const long long*)ei;
        r = (int)p[e];
        c = (int)p[N_EDGES + e];
    } else {
        const int* p = (const int*)ei;
        r = p[e];
        c = p[N_EDGES + e];
    }
}

// ---------------------------------------------------------------------------
__global__ void k_detect(const long long* __restrict__ ei64) {
    int ok = 1;
    for (int i = 0; i < 32; i++) {
        long long v = ei64[i];
        if (v < 0 || v >= N_NODES) { ok = 0; break; }
    }
    g_idx64 = ok;
}

// ---------------------------------------------------------------------------
__global__ void k_zero() {
    int i = blockIdx.x * blockDim.x + threadIdx.x;
    int stride = gridDim.x * blockDim.x;
    float4 z = make_float4(0.f, 0.f, 0.f, 0.f);
    float4* a4 = reinterpret_cast<float4*>(g_agg);
    float4* g4 = reinterpret_cast<float4*>(g_gg);
    const int n4 = N_NODES * D / 4;
    for (int idx = i; idx < n4; idx += stride) { a4[idx] = z; g4[idx] = z; }
    for (int idx = i; idx < N_NODES; idx += stride) { g_indeg[idx] = 0.f; g_outdeg[idx] = 0.f; }
}

// ---------------------------------------------------------------------------
// K2: scatter-sum X[row] into g_agg[col] + fused in-degree count.
// ---------------------------------------------------------------------------
__global__ void k_scatter(const float4* __restrict__ X4,
                          const void* __restrict__ ei) {
    long long gtid = (long long)blockIdx.x * blockDim.x + threadIdx.x;
    long long e = gtid >> 4;
    int l = (int)(gtid & 15);
    if (e >= N_EDGES) return;
    int is64 = g_idx64;
    int r, c;
    load_edge(ei, e, is64, r, c);
    float4 v = X4[(long long)r * 16 + l];
    red_add_v4(&g_agg[(long long)c * 64 + l * 4], v.x, v.y, v.z, v.w);
    if (l == 0) atomicAdd(&g_indeg[c], 1.f);
}

// ---------------------------------------------------------------------------
// K3: h = relu( (agg/indeg) @ Wl + b + X @ Wr ).
// Register-blocked: 64-node tile / block, thread = 4 nodes x 4 outputs.
// Inner loop: 4 x LDS.128 -> 32 FFMA.
// Dynamic smem layout (floats): sWl[4096] sWr[4096] saT[4096] sxT[4096]
//   saT/sxT are k-major: saT[k*64 + n].
// ---------------------------------------------------------------------------
__global__ __launch_bounds__(256) void k_h(const float* __restrict__ X,
                                           const float* __restrict__ Wl,
                                           const float* __restrict__ Wr,
                                           const float* __restrict__ b) {
    extern __shared__ float s[];
    float* sWl = s;
    float* sWr = s + 4096;
    float* saT = s + 8192;
    float* sxT = s + 12288;

    int t = threadIdx.x;
    for (int i = t; i < 4096; i += 256) { sWl[i] = Wl[i]; sWr[i] = Wr[i]; }

    const int jq = t & 15;        // j-group: outputs jq*4 .. jq*4+3
    const int ng = t >> 4;        // node-group: nodes ng*4 .. ng*4+3
    const float4 bias = reinterpret_cast<const float4*>(b)[jq];
    __syncthreads();

    const float4* A4 = reinterpret_cast<const float4*>(g_agg);
    const float4* X4 = reinterpret_cast<const float4*>(X);

    for (int base = blockIdx.x * 64; base < N_NODES; base += gridDim.x * 64) {
        // ---- load 64-node tile, transposed, with 1/indeg folded in ----
#pragma unroll
        for (int p = 0; p < 4; p++) {
            int fi = t + p * 256;          // 0..1023
            int node = fi & 63;
            int kq = fi >> 6;              // 0..15 (float4 index along k)
            int gnode = base + node;
            float4 va, vx;
            if (gnode < N_NODES) {
                float invd = 1.f / fmaxf(g_indeg[gnode], 1.f);
                va = A4[(long long)gnode * 16 + kq];
                vx = X4[(long long)gnode * 16 + kq];
                va.x *= invd; va.y *= invd; va.z *= invd; va.w *= invd;
            } else {
                va = make_float4(0.f, 0.f, 0.f, 0.f);
                vx = va;
            }
            int kb = kq * 4;
            saT[(kb + 0) * 64 + node] = va.x;
            saT[(kb + 1) * 64 + node] = va.y;
            saT[(kb + 2) * 64 + node] = va.z;
            saT[(kb + 3) * 64 + node] = va.w;
            sxT[(kb + 0) * 64 + node] = vx.x;
            sxT[(kb + 1) * 64 + node] = vx.y;
            sxT[(kb + 2) * 64 + node] = vx.z;
            sxT[(kb + 3) * 64 + node] = vx.w;
        }
        __syncthreads();

        // ---- compute 4x4 register block ----
        float acc[4][4];
#pragma unroll
        for (int i = 0; i < 4; i++) {
            acc[i][0] = bias.x; acc[i][1] = bias.y;
            acc[i][2] = bias.z; acc[i][3] = bias.w;
        }
#pragma unroll 8
        for (int k = 0; k < 64; k++) {
            float4 a4 = *reinterpret_cast<float4*>(&saT[k * 64 + ng * 4]);
            float4 x4 = *reinterpret_cast<float4*>(&sxT[k * 64 + ng * 4]);
            float4 wl = *reinterpret_cast<float4*>(&sWl[k * 64 + jq * 4]);
            float4 wr = *reinterpret_cast<float4*>(&sWr[k * 64 + jq * 4]);
            float av[4] = {a4.x, a4.y, a4.z, a4.w};
            float xv[4] = {x4.x, x4.y, x4.z, x4.w};
            float wlv[4] = {wl.x, wl.y, wl.z, wl.w};
            float wrv[4] = {wr.x, wr.y, wr.z, wr.w};
#pragma unroll
            for (int i = 0; i < 4; i++)
#pragma unroll
                for (int j = 0; j < 4; j++)
                    acc[i][j] += av[i] * wlv[j] + xv[i] * wrv[j];
        }

        // ---- store with ReLU ----
#pragma unroll
        for (int i = 0; i < 4; i++) {
            int node = base + ng * 4 + i;
            if (node < N_NODES) {
                float4 o;
                o.x = fmaxf(acc[i][0], 0.f);
                o.y = fmaxf(acc[i][1], 0.f);
                o.z = fmaxf(acc[i][2], 0.f);
                o.w = fmaxf(acc[i][3], 0.f);
                reinterpret_cast<float4*>(&g_h[(long long)node * 64])[jq] = o;
            }
        }
        __syncthreads();
    }
}

// ---------------------------------------------------------------------------
// K4: per-edge (h[row]-h[col])^2, scatter-sum at row + fused out-degree.
// ---------------------------------------------------------------------------
__global__ void k_edge(const void* __restrict__ ei) {
    long long gtid = (long long)blockIdx.x * blockDim.x + threadIdx.x;
    long long e = gtid >> 4;
    int l = (int)(gtid & 15);
    if (e >= N_EDGES) return;
    int is64 = g_idx64;
    int r, c;
    load_edge(ei, e, is64, r, c);
    const float4* h4 = reinterpret_cast<const float4*>(g_h);
    float4 u = h4[(long long)r * 16 + l];
    float4 v = h4[(long long)c * 16 + l];
    float dx = u.x - v.x, dy = u.y - v.y, dz = u.z - v.z, dw = u.w - v.w;
    red_add_v4(&g_gg[(long long)r * 64 + l * 4],
               dx * dx, dy * dy, dz * dz, dw * dw);
    if (l == 0) atomicAdd(&g_outdeg[r], 1.f);
}

// ---------------------------------------------------------------------------
__global__ void k_final(float* __restrict__ out) {
    int i = blockIdx.x * blockDim.x + threadIdx.x;
    int stride = gridDim.x * blockDim.x;
    for (int idx = i; idx < N_NODES * D; idx += stride) {
        int node = idx >> 6;
        float m = g_gg[idx] / fmaxf(g_outdeg[node], 1.f);
        out[idx] = tanhf(m);
    }
}

// ---------------------------------------------------------------------------
extern "C" void kernel_launch(void* const* d_in, const int* in_sizes, int n_in,
                              void* d_out, int out_size) {
    const float* X  = (const float*)d_in[0];
    const void*  ei = d_in[1];
    const float* Wl = (const float*)d_in[2];
    const float* Wr = (const float*)d_in[3];
    const float* b  = (const float*)d_in[4];
    float* out = (float*)d_out;

    const int KH_SMEM = 16384 * sizeof(float);   // 64 KB
    static int attr_done = 0;
    if (!attr_done) {
        cudaFuncSetAttribute(k_h, cudaFuncAttributeMaxDynamicSharedMemorySize,
                             KH_SMEM);
        attr_done = 1;
    }

    k_detect<<<1, 1>>>((const long long*)ei);
    k_zero<<<2048, 256>>>();
    {
        long long total = (long long)N_EDGES * 16;
        int blocks = (int)((total + 255) / 256);
        k_scatter<<<blocks, 256>>>((const float4*)X, ei);
    }
    k_h<<<444, 256, KH_SMEM>>>(X, Wl, Wr, b);
    {
        long long total = (long long)N_EDGES * 16;
        int blocks = (int)((total + 255) / 256);
        k_edge<<<blocks, 256>>>(ei);
    }
    k_final<<<2048, 256>>>(out);
}